// round 16
// baseline (speedup 1.0000x reference)
#include <cuda_runtime.h>
#include <cuda_fp16.h>
#include <math.h>

#define NN 50000
#define EE 800000
#define BB 64
#define DD 64
#define GG 50
#define HIDN 128
#define HD 128
#define LLAYERS 3
#define TBL 4096
#define TBL_SCALE 512.0f
#define SCAN_BLKS 49
#define TROWS 4
#define TBLK 1025            // ceil((TBL+1)/TROWS)

// ---- scratch ----
__device__ float  g_x[NN * DD];
__device__ uint4  g_hh[NN * 16];
__device__ float  g_v[NN * HD];
__device__ __align__(8) float g_el[NN * 2];
__device__ __align__(8) float g_er[NN * 2];
__device__ int    g_deg[NN];
__device__ int    g_rowptr[NN + 1];
__device__ int    g_wpos[NN];
__device__ int    g_btot[SCAN_BLKS];
__device__ float2 g_su[EE];
__device__ __half g_Tn[LLAYERS * (TBL + 1) * HD];   // 3.1 MB

__device__ __forceinline__ float ssp(float x) {
    return fmaxf(x, 0.f) + log1pf(expf(-fabsf(x))) - 0.69314718055994531f;
}

// ---------------- CSR build ----------------
__global__ void zero_deg(float* out) {
    int i = blockIdx.x * blockDim.x + threadIdx.x;
    if (i < NN) g_deg[i] = 0;
    if (i < BB) out[i] = 0.f;
}
__global__ void count_deg(const int* __restrict__ dst) {
    int e = blockIdx.x * blockDim.x + threadIdx.x;
    if (e < EE) atomicAdd(&g_deg[dst[e]], 1);
}
__global__ void scan1() {
    __shared__ int sh[1024];
    int t = threadIdx.x;
    int idx = blockIdx.x * 1024 + t;
    int v = (idx < NN) ? g_deg[idx] : 0;
    sh[t] = v;
    __syncthreads();
#pragma unroll
    for (int o = 1; o < 1024; o <<= 1) {
        int x = (t >= o) ? sh[t - o] : 0;
        __syncthreads();
        sh[t] += x;
        __syncthreads();
    }
    if (idx < NN) g_wpos[idx] = sh[t];
    if (t == 1023) g_btot[blockIdx.x] = sh[1023];
}
// fused: per-block recompute of the 49-entry block-offset prefix + final rowptr
__global__ void scan3() {
    __shared__ int sh[64];
    int t = threadIdx.x;
    if (t < 64) {
        int v = (t < SCAN_BLKS) ? g_btot[t] : 0;
        sh[t] = v;
    }
    __syncthreads();
#pragma unroll
    for (int o = 1; o < 64; o <<= 1) {
        int x = 0;
        if (t < 64 && t >= o) x = sh[t - o];
        __syncthreads();
        if (t < 64) sh[t] += x;
        __syncthreads();
    }
    int idx = blockIdx.x * blockDim.x + t;
    if (idx < NN) {
        int b = idx >> 10;
        int boff = (b > 0) ? sh[b - 1] : 0;
        int excl = boff + g_wpos[idx] - g_deg[idx];
        g_rowptr[idx] = excl;
        g_wpos[idx] = excl;
    }
    if (idx == 0) g_rowptr[NN] = sh[SCAN_BLKS - 1];
}
__global__ void scatter_kernel(const float* __restrict__ R,
                               const int* __restrict__ src,
                               const int* __restrict__ dst) {
    int e = blockIdx.x * blockDim.x + threadIdx.x;
    if (e >= EE) return;
    int s = src[e], d = dst[e];
    float dx = R[s * 3 + 0] - R[d * 3 + 0];
    float dy = R[s * 3 + 1] - R[d * 3 + 1];
    float dz = R[s * 3 + 2] - R[d * 3 + 2];
    float r = sqrtf(dx * dx + dy * dy + dz * dz);
    int pos = atomicAdd(&g_wpos[d], 1);
    float u = (r < 8.0f) ? r * TBL_SCALE : (float)TBL;
    g_su[pos] = make_float2(u, __int_as_float(s));
}

// ---------------- all-layer table build, 4 rows/block ----------------
__global__ void __launch_bounds__(128) build_tables(const float* __restrict__ off,
                                                    const float* __restrict__ wid,
                                                    const float* __restrict__ fw1,
                                                    const float* __restrict__ fb1,
                                                    const float* __restrict__ fw2,
                                                    const float* __restrict__ fb2) {
    int blk = blockIdx.x;
    int l = blk / TBLK;
    int i0 = (blk % TBLK) * TROWS;
    int t = threadIdx.x;
    const float* w1 = fw1 + l * GG * HD;
    const float* b1 = fb1 + l * HD;
    const float* w2 = fw2 + l * HIDN * HD;
    const float* b2 = fb2 + l * HD;
    __shared__ float gs[TROWS][GG];
    __shared__ float hid[TROWS][HIDN];
    if (t < GG) {
        float w = wid[t];
        float coef = -0.5f / (w * w);
        float o = off[t];
#pragma unroll
        for (int q = 0; q < TROWS; q++) {
            float r = (float)(i0 + q) * (8.0f / (float)TBL);
            float dr = r - o;
            gs[q][t] = expf(coef * dr * dr);
        }
    }
    __syncthreads();
    float acc[TROWS];
    float bb = b1[t];
#pragma unroll
    for (int q = 0; q < TROWS; q++) acc[q] = bb;
    for (int g = 0; g < GG; g++) {
        float w = w1[g * HD + t];
#pragma unroll
        for (int q = 0; q < TROWS; q++) acc[q] = fmaf(gs[q][g], w, acc[q]);
    }
#pragma unroll
    for (int q = 0; q < TROWS; q++) hid[q][t] = ssp(acc[q]);
    __syncthreads();
    float bb2 = b2[t];
#pragma unroll
    for (int q = 0; q < TROWS; q++) acc[q] = bb2;
    for (int k = 0; k < HIDN; k++) {
        float w = w2[k * HD + t];
#pragma unroll
        for (int q = 0; q < TROWS; q++) acc[q] = fmaf(hid[q][k], w, acc[q]);
    }
#pragma unroll
    for (int q = 0; q < TROWS; q++) {
        int i = i0 + q;
        if (i > TBL) continue;
        float r = (float)i * (8.0f / (float)TBL);
        float C = (r < 8.0f) ? 0.5f * (cosf(r * 0.39269908169872414f) + 1.0f) : 0.0f;
        float v = acc[q] * C;
        if (i == TBL) v = 0.f;
        g_Tn[(l * (TBL + 1) + i) * HD + t] = __float2half(v);
    }
}

// ---------------- pre phase macro (32 nodes in xs[32*65]) ----------------
#define PRE_PHASE(fcw, al, ar)                                                     \
    {                                                                              \
        int nA = t & 15, nB2 = nA + 16, cg = t >> 4;                               \
        float aA[8], aB[8];                                                        \
        _Pragma("unroll")                                                          \
        for (int j = 0; j < 8; j++) { aA[j] = 0.f; aB[j] = 0.f; }                  \
        const float4* W4 = (const float4*)(fcw);                                   \
        _Pragma("unroll 4")                                                        \
        for (int k = 0; k < 64; k++) {                                             \
            float xA = xs[nA * 65 + k];                                            \
            float xB = xs[nB2 * 65 + k];                                           \
            float4 wa = W4[k * 32 + cg * 2];                                       \
            float4 wb = W4[k * 32 + cg * 2 + 1];                                   \
            aA[0] = fmaf(xA, wa.x, aA[0]); aB[0] = fmaf(xB, wa.x, aB[0]);          \
            aA[1] = fmaf(xA, wa.y, aA[1]); aB[1] = fmaf(xB, wa.y, aB[1]);          \
            aA[2] = fmaf(xA, wa.z, aA[2]); aB[2] = fmaf(xB, wa.z, aB[2]);          \
            aA[3] = fmaf(xA, wa.w, aA[3]); aB[3] = fmaf(xB, wa.w, aB[3]);          \
            aA[4] = fmaf(xA, wb.x, aA[4]); aB[4] = fmaf(xB, wb.x, aB[4]);          \
            aA[5] = fmaf(xA, wb.y, aA[5]); aB[5] = fmaf(xB, wb.y, aB[5]);          \
            aA[6] = fmaf(xA, wb.z, aA[6]); aB[6] = fmaf(xB, wb.z, aB[6]);          \
            aA[7] = fmaf(xA, wb.w, aA[7]); aB[7] = fmaf(xB, wb.w, aB[7]);          \
        }                                                                          \
        bool vA = (n0 + nA) < NN, vB = (n0 + nB2) < NN;                            \
        __half2 hp[4];                                                             \
        hp[0] = __floats2half2_rn(aA[0], aA[1]);                                   \
        hp[1] = __floats2half2_rn(aA[2], aA[3]);                                   \
        hp[2] = __floats2half2_rn(aA[4], aA[5]);                                   \
        hp[3] = __floats2half2_rn(aA[6], aA[7]);                                   \
        if (vA) g_hh[(n0 + nA) * 16 + cg] = *reinterpret_cast<uint4*>(hp);         \
        hp[0] = __floats2half2_rn(aB[0], aB[1]);                                   \
        hp[1] = __floats2half2_rn(aB[2], aB[3]);                                   \
        hp[2] = __floats2half2_rn(aB[4], aB[5]);                                   \
        hp[3] = __floats2half2_rn(aB[6], aB[7]);                                   \
        if (vB) g_hh[(n0 + nB2) * 16 + cg] = *reinterpret_cast<uint4*>(hp);        \
        int head = cg >> 3;                                                        \
        int ca = (cg * 8) & 63;                                                    \
        float4 ala = ((const float4*)(al))[head * 16 + (ca >> 2)];                 \
        float4 alb = ((const float4*)(al))[head * 16 + (ca >> 2) + 1];             \
        float4 ara = ((const float4*)(ar))[head * 16 + (ca >> 2)];                 \
        float4 arb = ((const float4*)(ar))[head * 16 + (ca >> 2) + 1];             \
        float plA = aA[0]*ala.x + aA[1]*ala.y + aA[2]*ala.z + aA[3]*ala.w          \
                  + aA[4]*alb.x + aA[5]*alb.y + aA[6]*alb.z + aA[7]*alb.w;         \
        float prA = aA[0]*ara.x + aA[1]*ara.y + aA[2]*ara.z + aA[3]*ara.w          \
                  + aA[4]*arb.x + aA[5]*arb.y + aA[6]*arb.z + aA[7]*arb.w;         \
        float plB = aB[0]*ala.x + aB[1]*ala.y + aB[2]*ala.z + aB[3]*ala.w          \
                  + aB[4]*alb.x + aB[5]*alb.y + aB[6]*alb.z + aB[7]*alb.w;         \
        float prB = aB[0]*ara.x + aB[1]*ara.y + aB[2]*ara.z + aB[3]*ara.w          \
                  + aB[4]*arb.x + aB[5]*arb.y + aB[6]*arb.z + aB[7]*arb.w;         \
        atomicAdd(&els[nA * 2 + head], plA);                                       \
        atomicAdd(&ers[nA * 2 + head], prA);                                       \
        atomicAdd(&els[nB2 * 2 + head], plB);                                      \
        atomicAdd(&ers[nB2 * 2 + head], prB);                                      \
        __syncthreads();                                                           \
        if (t < 64 && (n0 + (t >> 1)) < NN) {                                      \
            g_el[n0 * 2 + t] = els[t];                                             \
            g_er[n0 * 2 + t] = ers[t];                                             \
        }                                                                          \
    }

// ---------------- layer 0: embed + pre ----------------
__global__ void __launch_bounds__(256) pre_first(const int* __restrict__ Z,
                                                 const float* __restrict__ emb,
                                                 const float* __restrict__ fcw,
                                                 const float* __restrict__ al,
                                                 const float* __restrict__ ar) {
    int n0 = blockIdx.x * 32;
    int t = threadIdx.x;
    __shared__ float xs[32 * 65];
    __shared__ float els[64], ers[64];
    for (int i = t; i < 32 * 64; i += 256) {
        int node = n0 + (i >> 6);
        float v = 0.f;
        if (node < NN) {
            v = emb[Z[node] * DD + (i & 63)];
            g_x[node * DD + (i & 63)] = v;
        }
        xs[(i >> 6) * 65 + (i & 63)] = v;
    }
    if (t < 64) { els[t] = 0.f; ers[t] = 0.f; }
    __syncthreads();
    PRE_PHASE(fcw, al, ar)
}

// ---------------- gather: warp/node, fixed 8-edge unrolled blocks ----------------
// Padded lanes carry u=0, s=0, e0=e1=0: table row 0 and node 0's h row are valid
// memory, and ex==0 makes the padded contribution exactly zero (numerator AND
// denominator). Rounding cnt up to a multiple of 8 lets ptxas fully unroll the
// inner block and front-batch 16 independent LDGs per 8 edges.
#define EDGE_BODY(cc)                                                     \
    {                                                                     \
        float uc = __shfl_sync(0xffffffffu, u, (cc));                     \
        int   sc = __shfl_sync(0xffffffffu, s, (cc));                     \
        float p0 = __shfl_sync(0xffffffffu, e0, (cc));                    \
        float p1 = __shfl_sync(0xffffffffu, e1, (cc));                    \
        int ii = (int)(uc + 0.5f);                                        \
        uint2 tw = *((const uint2*)(Tp + ii * HD) + lane);                \
        uint2 hw = *((const uint2*)(hh + sc * HD) + lane);                \
        float ex = (lane < 16) ? p0 : p1;                                 \
        __half2 q0 = __hmul2(*(__half2*)&tw.x, *(__half2*)&hw.x);         \
        __half2 q1 = __hmul2(*(__half2*)&tw.y, *(__half2*)&hw.y);         \
        float2 f0 = __half22float2(q0);                                   \
        float2 f1 = __half22float2(q1);                                   \
        a0 = fmaf(f0.x, ex, a0);                                          \
        a1 = fmaf(f0.y, ex, a1);                                          \
        a2 = fmaf(f1.x, ex, a2);                                          \
        a3 = fmaf(f1.y, ex, a3);                                          \
        exs += ex;                                                        \
    }

__global__ void __launch_bounds__(256) gather_v(int l) {
    const __half* Tp = g_Tn + (size_t)l * (TBL + 1) * HD;
    int wid = threadIdx.x >> 5, lane = threadIdx.x & 31;
    int n = blockIdx.x * 8 + wid;
    if (n >= NN) return;
    int beg = g_rowptr[n], end = g_rowptr[n + 1];
    float2 er = ((const float2*)g_er)[n];
    float a0 = 0.f, a1 = 0.f, a2 = 0.f, a3 = 0.f, exs = 0.f;
    const __half* hh = (const __half*)g_hh;
    for (int base = beg; base < end; base += 32) {
        int cnt = min(32, end - base);
        float u = 0.f, e0 = 0.f, e1 = 0.f;
        int s = 0;
        if (lane < cnt) {
            float2 su = g_su[base + lane];
            u = su.x;
            s = __float_as_int(su.y);
            float2 el = ((const float2*)g_el)[s];
            float ev0 = el.x + er.x; ev0 = ev0 > 0.f ? ev0 : 0.2f * ev0;
            float ev1 = el.y + er.y; ev1 = ev1 > 0.f ? ev1 : 0.2f * ev1;
            e0 = __expf(ev0);
            e1 = __expf(ev1);
        }
        int cntR = (cnt + 7) & ~7;            // pad to multiple of 8 (zero-contrib)
        for (int c0 = 0; c0 < cntR; c0 += 8) {
#pragma unroll
            for (int q = 0; q < 8; q++) {
                EDGE_BODY(c0 + q)
            }
        }
    }
    float inv = (exs > 0.f) ? 1.0f / exs : 0.f;
    float4 o;
    o.x = ssp(a0 * inv);
    o.y = ssp(a1 * inv);
    o.z = ssp(a2 * inv);
    o.w = ssp(a3 * inv);
    ((float4*)g_v)[n * 32 + lane] = o;
}

// ---------------- fused: mlp(layer l) + pre(layer l+1) ----------------
__global__ void __launch_bounds__(256) mlp_pre(const float* __restrict__ m1,
                                               const float* __restrict__ mb1,
                                               const float* __restrict__ m2,
                                               const float* __restrict__ mb2,
                                               const float* __restrict__ fcw,
                                               const float* __restrict__ al,
                                               const float* __restrict__ ar) {
    int n0 = blockIdx.x * 32;
    int t = threadIdx.x;
    __shared__ float vs[32 * 129];
    __shared__ float t1s[32 * 65];
    __shared__ float xs[32 * 65];
    __shared__ float els[64], ers[64];
    for (int i = t; i < 32 * 128; i += 256) {
        int node = n0 + (i >> 7);
        vs[(i >> 7) * 129 + (i & 127)] = (node < NN) ? g_v[node * 128 + (i & 127)] : 0.f;
    }
    if (t < 64) { els[t] = 0.f; ers[t] = 0.f; }
    __syncthreads();
    {
        int nA = t & 15, nB2 = nA + 16, cg = t >> 4;
        float aA0 = 0.f, aA1 = 0.f, aA2 = 0.f, aA3 = 0.f;
        float aB0 = 0.f, aB1 = 0.f, aB2 = 0.f, aB3 = 0.f;
        const float4* M1 = (const float4*)m1;
#pragma unroll 4
        for (int k = 0; k < 128; k++) {
            float xA = vs[nA * 129 + k];
            float xB = vs[nB2 * 129 + k];
            float4 w = M1[k * 16 + cg];
            aA0 = fmaf(xA, w.x, aA0); aB0 = fmaf(xB, w.x, aB0);
            aA1 = fmaf(xA, w.y, aA1); aB1 = fmaf(xB, w.y, aB1);
            aA2 = fmaf(xA, w.z, aA2); aB2 = fmaf(xB, w.z, aB2);
            aA3 = fmaf(xA, w.w, aA3); aB3 = fmaf(xB, w.w, aB3);
        }
        float4 b14 = ((const float4*)mb1)[cg];
        t1s[nA * 65 + cg * 4 + 0] = ssp(aA0 + b14.x);
        t1s[nA * 65 + cg * 4 + 1] = ssp(aA1 + b14.y);
        t1s[nA * 65 + cg * 4 + 2] = ssp(aA2 + b14.z);
        t1s[nA * 65 + cg * 4 + 3] = ssp(aA3 + b14.w);
        t1s[nB2 * 65 + cg * 4 + 0] = ssp(aB0 + b14.x);
        t1s[nB2 * 65 + cg * 4 + 1] = ssp(aB1 + b14.y);
        t1s[nB2 * 65 + cg * 4 + 2] = ssp(aB2 + b14.z);
        t1s[nB2 * 65 + cg * 4 + 3] = ssp(aB3 + b14.w);
        __syncthreads();
        aA0 = aA1 = aA2 = aA3 = 0.f;
        aB0 = aB1 = aB2 = aB3 = 0.f;
        const float4* M2 = (const float4*)m2;
#pragma unroll 4
        for (int k = 0; k < 64; k++) {
            float xA = t1s[nA * 65 + k];
            float xB = t1s[nB2 * 65 + k];
            float4 w = M2[k * 16 + cg];
            aA0 = fmaf(xA, w.x, aA0); aB0 = fmaf(xB, w.x, aB0);
            aA1 = fmaf(xA, w.y, aA1); aB1 = fmaf(xB, w.y, aB1);
            aA2 = fmaf(xA, w.z, aA2); aB2 = fmaf(xB, w.z, aB2);
            aA3 = fmaf(xA, w.w, aA3); aB3 = fmaf(xB, w.w, aB3);
        }
        float4 b24 = ((const float4*)mb2)[cg];
        bool vA = (n0 + nA) < NN, vB = (n0 + nB2) < NN;
        float4 xA4 = make_float4(0.f, 0.f, 0.f, 0.f);
        float4 xB4 = make_float4(0.f, 0.f, 0.f, 0.f);
        if (vA) xA4 = ((float4*)g_x)[(n0 + nA) * 16 + cg];
        if (vB) xB4 = ((float4*)g_x)[(n0 + nB2) * 16 + cg];
        xA4.x += aA0 + b24.x; xA4.y += aA1 + b24.y;
        xA4.z += aA2 + b24.z; xA4.w += aA3 + b24.w;
        xB4.x += aB0 + b24.x; xB4.y += aB1 + b24.y;
        xB4.z += aB2 + b24.z; xB4.w += aB3 + b24.w;
        if (vA) ((float4*)g_x)[(n0 + nA) * 16 + cg] = xA4;
        if (vB) ((float4*)g_x)[(n0 + nB2) * 16 + cg] = xB4;
        xs[nA * 65 + cg * 4 + 0] = xA4.x;
        xs[nA * 65 + cg * 4 + 1] = xA4.y;
        xs[nA * 65 + cg * 4 + 2] = xA4.z;
        xs[nA * 65 + cg * 4 + 3] = xA4.w;
        xs[nB2 * 65 + cg * 4 + 0] = xB4.x;
        xs[nB2 * 65 + cg * 4 + 1] = xB4.y;
        xs[nB2 * 65 + cg * 4 + 2] = xB4.z;
        xs[nB2 * 65 + cg * 4 + 3] = xB4.w;
    }
    __syncthreads();
    PRE_PHASE(fcw, al, ar)
}

// ---------------- fused: mlp(last layer) + output head ----------------
__global__ void __launch_bounds__(256) mlp_out(const float* __restrict__ m1,
                                               const float* __restrict__ mb1,
                                               const float* __restrict__ m2,
                                               const float* __restrict__ mb2,
                                               const float* __restrict__ w1o,
                                               const float* __restrict__ b1o,
                                               const float* __restrict__ w2o,
                                               const float* __restrict__ b2o,
                                               const int* __restrict__ gid,
                                               float* __restrict__ out) {
    int n0 = blockIdx.x * 16;          // 3125 blocks exact
    int t = threadIdx.x;
    __shared__ float vs[16 * 129];
    __shared__ float t1s[16 * 65];
    __shared__ float xs[16 * 65];
    __shared__ float sred[16][17];
    for (int i = t; i < 16 * 128; i += 256)
        vs[(i >> 7) * 129 + (i & 127)] = g_v[n0 * 128 + i];
    __syncthreads();
    int n = t & 15, cg = t >> 4;
    {
        float a0 = 0.f, a1 = 0.f, a2 = 0.f, a3 = 0.f;
        const float4* M1 = (const float4*)m1;
#pragma unroll 4
        for (int k = 0; k < 128; k++) {
            float xv = vs[n * 129 + k];
            float4 w = M1[k * 16 + cg];
            a0 = fmaf(xv, w.x, a0);
            a1 = fmaf(xv, w.y, a1);
            a2 = fmaf(xv, w.z, a2);
            a3 = fmaf(xv, w.w, a3);
        }
        float4 b14 = ((const float4*)mb1)[cg];
        t1s[n * 65 + cg * 4 + 0] = ssp(a0 + b14.x);
        t1s[n * 65 + cg * 4 + 1] = ssp(a1 + b14.y);
        t1s[n * 65 + cg * 4 + 2] = ssp(a2 + b14.z);
        t1s[n * 65 + cg * 4 + 3] = ssp(a3 + b14.w);
        __syncthreads();
        a0 = a1 = a2 = a3 = 0.f;
        const float4* M2 = (const float4*)m2;
#pragma unroll 4
        for (int k = 0; k < 64; k++) {
            float xv = t1s[n * 65 + k];
            float4 w = M2[k * 16 + cg];
            a0 = fmaf(xv, w.x, a0);
            a1 = fmaf(xv, w.y, a1);
            a2 = fmaf(xv, w.z, a2);
            a3 = fmaf(xv, w.w, a3);
        }
        float4 b24 = ((const float4*)mb2)[cg];
        float4 x4 = ((const float4*)g_x)[(n0 + n) * 16 + cg];
        xs[n * 65 + cg * 4 + 0] = x4.x + a0 + b24.x;
        xs[n * 65 + cg * 4 + 1] = x4.y + a1 + b24.y;
        xs[n * 65 + cg * 4 + 2] = x4.z + a2 + b24.z;
        xs[n * 65 + cg * 4 + 3] = x4.w + a3 + b24.w;
    }
    __syncthreads();
    float acc[8];
#pragma unroll
    for (int j = 0; j < 8; j++) acc[j] = 0.f;
    const float4* W4 = (const float4*)w1o;
#pragma unroll 4
    for (int k = 0; k < 64; k++) {
        float xv = xs[n * 65 + k];
        float4 wa = W4[k * 32 + cg * 2];
        float4 wb = W4[k * 32 + cg * 2 + 1];
        acc[0] = fmaf(xv, wa.x, acc[0]);
        acc[1] = fmaf(xv, wa.y, acc[1]);
        acc[2] = fmaf(xv, wa.z, acc[2]);
        acc[3] = fmaf(xv, wa.w, acc[3]);
        acc[4] = fmaf(xv, wb.x, acc[4]);
        acc[5] = fmaf(xv, wb.y, acc[5]);
        acc[6] = fmaf(xv, wb.z, acc[6]);
        acc[7] = fmaf(xv, wb.w, acc[7]);
    }
    float4 b1a = ((const float4*)b1o)[cg * 2];
    float4 b1b = ((const float4*)b1o)[cg * 2 + 1];
    float4 w2a = ((const float4*)w2o)[cg * 2];
    float4 w2b = ((const float4*)w2o)[cg * 2 + 1];
    float p = ssp(acc[0] + b1a.x) * w2a.x + ssp(acc[1] + b1a.y) * w2a.y
            + ssp(acc[2] + b1a.z) * w2a.z + ssp(acc[3] + b1a.w) * w2a.w
            + ssp(acc[4] + b1b.x) * w2b.x + ssp(acc[5] + b1b.y) * w2b.y
            + ssp(acc[6] + b1b.z) * w2b.z + ssp(acc[7] + b1b.w) * w2b.w;
    sred[cg][n] = p;
    __syncthreads();
    if (t < 16) {
        float s = b2o[0];
#pragma unroll
        for (int c = 0; c < 16; c++) s += sred[c][t];
        atomicAdd(&out[gid[n0 + t]], s);
    }
}

extern "C" void kernel_launch(void* const* d_in, const int* in_sizes, int n_in,
                              void* d_out, int out_size) {
    const float* R    = (const float*)d_in[0];
    const int*   Z    = (const int*)d_in[1];
    const int*   src  = (const int*)d_in[2];
    const int*   dst  = (const int*)d_in[3];
    const int*   gid  = (const int*)d_in[4];
    const float* emb  = (const float*)d_in[5];
    const float* off  = (const float*)d_in[6];
    const float* wid  = (const float*)d_in[7];
    const float* fcw  = (const float*)d_in[8];
    const float* al   = (const float*)d_in[9];
    const float* ar   = (const float*)d_in[10];
    const float* fw1  = (const float*)d_in[11];
    const float* fb1  = (const float*)d_in[12];
    const float* fw2  = (const float*)d_in[13];
    const float* fb2  = (const float*)d_in[14];
    const float* m1   = (const float*)d_in[15];
    const float* mb1  = (const float*)d_in[16];
    const float* m2   = (const float*)d_in[17];
    const float* mb2  = (const float*)d_in[18];
    const float* ow1  = (const float*)d_in[19];
    const float* ob1  = (const float*)d_in[20];
    const float* ow2  = (const float*)d_in[21];
    const float* ob2  = (const float*)d_in[22];
    float* out = (float*)d_out;

    zero_deg<<<(NN + 255) / 256, 256>>>(out);
    build_tables<<<LLAYERS * TBLK, 128>>>(off, wid, fw1, fb1, fw2, fb2);
    count_deg<<<(EE + 255) / 256, 256>>>(dst);
    scan1<<<SCAN_BLKS, 1024>>>();
    scan3<<<(NN + 255) / 256, 256>>>();
    scatter_kernel<<<(EE + 255) / 256, 256>>>(R, src, dst);

    pre_first<<<(NN + 31) / 32, 256>>>(Z, emb, fcw, al, ar);
    gather_v<<<(NN + 7) / 8, 256>>>(0);
    mlp_pre<<<(NN + 31) / 32, 256>>>(m1, mb1, m2, mb2,
                                     fcw + 1 * DD * HD, al + 1 * 2 * DD, ar + 1 * 2 * DD);
    gather_v<<<(NN + 7) / 8, 256>>>(1);
    mlp_pre<<<(NN + 31) / 32, 256>>>(m1 + 1 * HD * DD, mb1 + 1 * DD, m2 + 1 * DD * DD, mb2 + 1 * DD,
                                     fcw + 2 * DD * HD, al + 2 * 2 * DD, ar + 2 * 2 * DD);
    gather_v<<<(NN + 7) / 8, 256>>>(2);
    mlp_out<<<NN / 16, 256>>>(m1 + 2 * HD * DD, mb1 + 2 * DD, m2 + 2 * DD * DD, mb2 + 2 * DD,
                              ow1, ob1, ow2, ob2, gid, out);
}

// round 17
// speedup vs baseline: 1.0361x; 1.0361x over previous
#include <cuda_runtime.h>
#include <cuda_fp16.h>
#include <cuda_fp8.h>
#include <math.h>

#define NN 50000
#define EE 800000
#define BB 64
#define DD 64
#define GG 50
#define HIDN 128
#define HD 128
#define LLAYERS 3
#define TBL 4096
#define TBL_SCALE 512.0f
#define SCAN_BLKS 49
#define TROWS 4
#define TBLK 1025            // ceil((TBL+1)/TROWS)

// ---- scratch ----
__device__ float  g_x[NN * DD];
__device__ __align__(16) unsigned g_h8[NN * 32];            // fp8 h: 128 fp8/node = 32 uints
__device__ float  g_v[NN * HD];
__device__ __align__(8) float g_el[NN * 2];
__device__ __align__(8) float g_er[NN * 2];
__device__ int    g_deg[NN];
__device__ int    g_rowptr[NN + 1];
__device__ int    g_wpos[NN];
__device__ int    g_btot[SCAN_BLKS];
__device__ float2 g_su[EE];
__device__ __align__(16) unsigned char g_T8[LLAYERS * (TBL + 1) * HD];  // fp8 table, 1.6 MB

__device__ __forceinline__ float ssp(float x) {
    return fmaxf(x, 0.f) + log1pf(expf(-fabsf(x))) - 0.69314718055994531f;
}

// ---------------- CSR build ----------------
__global__ void zero_deg(float* out) {
    int i = blockIdx.x * blockDim.x + threadIdx.x;
    if (i < NN) g_deg[i] = 0;
    if (i < BB) out[i] = 0.f;
}
__global__ void count_deg(const int* __restrict__ dst) {
    int e = blockIdx.x * blockDim.x + threadIdx.x;
    if (e < EE) atomicAdd(&g_deg[dst[e]], 1);
}
__global__ void scan1() {
    __shared__ int sh[1024];
    int t = threadIdx.x;
    int idx = blockIdx.x * 1024 + t;
    int v = (idx < NN) ? g_deg[idx] : 0;
    sh[t] = v;
    __syncthreads();
#pragma unroll
    for (int o = 1; o < 1024; o <<= 1) {
        int x = (t >= o) ? sh[t - o] : 0;
        __syncthreads();
        sh[t] += x;
        __syncthreads();
    }
    if (idx < NN) g_wpos[idx] = sh[t];
    if (t == 1023) g_btot[blockIdx.x] = sh[1023];
}
__global__ void scan3() {
    __shared__ int sh[64];
    int t = threadIdx.x;
    if (t < 64) {
        int v = (t < SCAN_BLKS) ? g_btot[t] : 0;
        sh[t] = v;
    }
    __syncthreads();
#pragma unroll
    for (int o = 1; o < 64; o <<= 1) {
        int x = 0;
        if (t < 64 && t >= o) x = sh[t - o];
        __syncthreads();
        if (t < 64) sh[t] += x;
        __syncthreads();
    }
    int idx = blockIdx.x * blockDim.x + t;
    if (idx < NN) {
        int b = idx >> 10;
        int boff = (b > 0) ? sh[b - 1] : 0;
        int excl = boff + g_wpos[idx] - g_deg[idx];
        g_rowptr[idx] = excl;
        g_wpos[idx] = excl;
    }
    if (idx == 0) g_rowptr[NN] = sh[SCAN_BLKS - 1];
}
__global__ void scatter_kernel(const float* __restrict__ R,
                               const int* __restrict__ src,
                               const int* __restrict__ dst) {
    int e = blockIdx.x * blockDim.x + threadIdx.x;
    if (e >= EE) return;
    int s = src[e], d = dst[e];
    float dx = R[s * 3 + 0] - R[d * 3 + 0];
    float dy = R[s * 3 + 1] - R[d * 3 + 1];
    float dz = R[s * 3 + 2] - R[d * 3 + 2];
    float r = sqrtf(dx * dx + dy * dy + dz * dz);
    int pos = atomicAdd(&g_wpos[d], 1);
    float u = (r < 8.0f) ? r * TBL_SCALE : (float)TBL;
    g_su[pos] = make_float2(u, __int_as_float(s));
}

// ---------------- all-layer fp8 table build, 4 rows/block ----------------
__global__ void __launch_bounds__(128) build_tables(const float* __restrict__ off,
                                                    const float* __restrict__ wid,
                                                    const float* __restrict__ fw1,
                                                    const float* __restrict__ fb1,
                                                    const float* __restrict__ fw2,
                                                    const float* __restrict__ fb2) {
    int blk = blockIdx.x;
    int l = blk / TBLK;
    int i0 = (blk % TBLK) * TROWS;
    int t = threadIdx.x;
    const float* w1 = fw1 + l * GG * HD;
    const float* b1 = fb1 + l * HD;
    const float* w2 = fw2 + l * HIDN * HD;
    const float* b2 = fb2 + l * HD;
    __shared__ float gs[TROWS][GG];
    __shared__ float hid[TROWS][HIDN];
    if (t < GG) {
        float w = wid[t];
        float coef = -0.5f / (w * w);
        float o = off[t];
#pragma unroll
        for (int q = 0; q < TROWS; q++) {
            float r = (float)(i0 + q) * (8.0f / (float)TBL);
            float dr = r - o;
            gs[q][t] = expf(coef * dr * dr);
        }
    }
    __syncthreads();
    float acc[TROWS];
    float bb = b1[t];
#pragma unroll
    for (int q = 0; q < TROWS; q++) acc[q] = bb;
    for (int g = 0; g < GG; g++) {
        float w = w1[g * HD + t];
#pragma unroll
        for (int q = 0; q < TROWS; q++) acc[q] = fmaf(gs[q][g], w, acc[q]);
    }
#pragma unroll
    for (int q = 0; q < TROWS; q++) hid[q][t] = ssp(acc[q]);
    __syncthreads();
    float bb2 = b2[t];
#pragma unroll
    for (int q = 0; q < TROWS; q++) acc[q] = bb2;
    for (int k = 0; k < HIDN; k++) {
        float w = w2[k * HD + t];
#pragma unroll
        for (int q = 0; q < TROWS; q++) acc[q] = fmaf(hid[q][k], w, acc[q]);
    }
#pragma unroll
    for (int q = 0; q < TROWS; q++) {
        int i = i0 + q;
        if (i > TBL) continue;
        float r = (float)i * (8.0f / (float)TBL);
        float C = (r < 8.0f) ? 0.5f * (cosf(r * 0.39269908169872414f) + 1.0f) : 0.0f;
        float v = acc[q] * C;
        if (i == TBL) v = 0.f;
        g_T8[(l * (TBL + 1) + i) * HD + t] =
            __nv_cvt_float_to_fp8(v, __NV_SATFINITE, __NV_E4M3);
    }
}

// ---------------- pre phase macro (32 nodes in xs[32*65]) ----------------
#define PRE_PHASE(fcw, al, ar)                                                     \
    {                                                                              \
        int nA = t & 15, nB2 = nA + 16, cg = t >> 4;                               \
        float aA[8], aB[8];                                                        \
        _Pragma("unroll")                                                          \
        for (int j = 0; j < 8; j++) { aA[j] = 0.f; aB[j] = 0.f; }                  \
        const float4* W4 = (const float4*)(fcw);                                   \
        _Pragma("unroll 4")                                                        \
        for (int k = 0; k < 64; k++) {                                             \
            float xA = xs[nA * 65 + k];                                            \
            float xB = xs[nB2 * 65 + k];                                           \
            float4 wa = W4[k * 32 + cg * 2];                                       \
            float4 wb = W4[k * 32 + cg * 2 + 1];                                   \
            aA[0] = fmaf(xA, wa.x, aA[0]); aB[0] = fmaf(xB, wa.x, aB[0]);          \
            aA[1] = fmaf(xA, wa.y, aA[1]); aB[1] = fmaf(xB, wa.y, aB[1]);          \
            aA[2] = fmaf(xA, wa.z, aA[2]); aB[2] = fmaf(xB, wa.z, aB[2]);          \
            aA[3] = fmaf(xA, wa.w, aA[3]); aB[3] = fmaf(xB, wa.w, aB[3]);          \
            aA[4] = fmaf(xA, wb.x, aA[4]); aB[4] = fmaf(xB, wb.x, aB[4]);          \
            aA[5] = fmaf(xA, wb.y, aA[5]); aB[5] = fmaf(xB, wb.y, aB[5]);          \
            aA[6] = fmaf(xA, wb.z, aA[6]); aB[6] = fmaf(xB, wb.z, aB[6]);          \
            aA[7] = fmaf(xA, wb.w, aA[7]); aB[7] = fmaf(xB, wb.w, aB[7]);          \
        }                                                                          \
        bool vA = (n0 + nA) < NN, vB = (n0 + nB2) < NN;                            \
        {                                                                          \
            unsigned pA0 = (unsigned)__nv_cvt_float2_to_fp8x2(                     \
                make_float2(aA[0], aA[1]), __NV_SATFINITE, __NV_E4M3);             \
            unsigned pA1 = (unsigned)__nv_cvt_float2_to_fp8x2(                     \
                make_float2(aA[2], aA[3]), __NV_SATFINITE, __NV_E4M3);             \
            unsigned pA2 = (unsigned)__nv_cvt_float2_to_fp8x2(                     \
                make_float2(aA[4], aA[5]), __NV_SATFINITE, __NV_E4M3);             \
            unsigned pA3 = (unsigned)__nv_cvt_float2_to_fp8x2(                     \
                make_float2(aA[6], aA[7]), __NV_SATFINITE, __NV_E4M3);             \
            if (vA) ((uint2*)g_h8)[(n0 + nA) * 16 + cg] =                          \
                make_uint2(pA0 | (pA1 << 16), pA2 | (pA3 << 16));                  \
            unsigned pB0 = (unsigned)__nv_cvt_float2_to_fp8x2(                     \
                make_float2(aB[0], aB[1]), __NV_SATFINITE, __NV_E4M3);             \
            unsigned pB1 = (unsigned)__nv_cvt_float2_to_fp8x2(                     \
                make_float2(aB[2], aB[3]), __NV_SATFINITE, __NV_E4M3);             \
            unsigned pB2 = (unsigned)__nv_cvt_float2_to_fp8x2(                     \
                make_float2(aB[4], aB[5]), __NV_SATFINITE, __NV_E4M3);             \
            unsigned pB3 = (unsigned)__nv_cvt_float2_to_fp8x2(                     \
                make_float2(aB[6], aB[7]), __NV_SATFINITE, __NV_E4M3);             \
            if (vB) ((uint2*)g_h8)[(n0 + nB2) * 16 + cg] =                         \
                make_uint2(pB0 | (pB1 << 16), pB2 | (pB3 << 16));                  \
        }                                                                          \
        int head = cg >> 3;                                                        \
        int ca = (cg * 8) & 63;                                                    \
        float4 ala = ((const float4*)(al))[head * 16 + (ca >> 2)];                 \
        float4 alb = ((const float4*)(al))[head * 16 + (ca >> 2) + 1];             \
        float4 ara = ((const float4*)(ar))[head * 16 + (ca >> 2)];                 \
        float4 arb = ((const float4*)(ar))[head * 16 + (ca >> 2) + 1];             \
        float plA = aA[0]*ala.x + aA[1]*ala.y + aA[2]*ala.z + aA[3]*ala.w          \
                  + aA[4]*alb.x + aA[5]*alb.y + aA[6]*alb.z + aA[7]*alb.w;         \
        float prA = aA[0]*ara.x + aA[1]*ara.y + aA[2]*ara.z + aA[3]*ara.w          \
                  + aA[4]*arb.x + aA[5]*arb.y + aA[6]*arb.z + aA[7]*arb.w;         \
        float plB = aB[0]*ala.x + aB[1]*ala.y + aB[2]*ala.z + aB[3]*ala.w          \
                  + aB[4]*alb.x + aB[5]*alb.y + aB[6]*alb.z + aB[7]*alb.w;         \
        float prB = aB[0]*ara.x + aB[1]*ara.y + aB[2]*ara.z + aB[3]*ara.w          \
                  + aB[4]*arb.x + aB[5]*arb.y + aB[6]*arb.z + aB[7]*arb.w;         \
        atomicAdd(&els[nA * 2 + head], plA);                                       \
        atomicAdd(&ers[nA * 2 + head], prA);                                       \
        atomicAdd(&els[nB2 * 2 + head], plB);                                      \
        atomicAdd(&ers[nB2 * 2 + head], prB);                                      \
        __syncthreads();                                                           \
        if (t < 64 && (n0 + (t >> 1)) < NN) {                                      \
            g_el[n0 * 2 + t] = els[t];                                             \
            g_er[n0 * 2 + t] = ers[t];                                             \
        }                                                                          \
    }

// ---------------- layer 0: embed + pre ----------------
__global__ void __launch_bounds__(256) pre_first(const int* __restrict__ Z,
                                                 const float* __restrict__ emb,
                                                 const float* __restrict__ fcw,
                                                 const float* __restrict__ al,
                                                 const float* __restrict__ ar) {
    int n0 = blockIdx.x * 32;
    int t = threadIdx.x;
    __shared__ float xs[32 * 65];
    __shared__ float els[64], ers[64];
    for (int i = t; i < 32 * 64; i += 256) {
        int node = n0 + (i >> 6);
        float v = 0.f;
        if (node < NN) {
            v = emb[Z[node] * DD + (i & 63)];
            g_x[node * DD + (i & 63)] = v;
        }
        xs[(i >> 6) * 65 + (i & 63)] = v;
    }
    if (t < 64) { els[t] = 0.f; ers[t] = 0.f; }
    __syncthreads();
    PRE_PHASE(fcw, al, ar)
}

// ---------------- gather: warp/node, R9 2-edge structure, fp8 operands ----------------
__device__ __forceinline__ void edge_mul_acc(unsigned tw, unsigned hw, float ex,
                                             float& a0, float& a1, float& a2, float& a3) {
    __half2_raw t01 = __nv_cvt_fp8x2_to_halfraw2((__nv_fp8x2_storage_t)(tw & 0xffffu), __NV_E4M3);
    __half2_raw t23 = __nv_cvt_fp8x2_to_halfraw2((__nv_fp8x2_storage_t)(tw >> 16), __NV_E4M3);
    __half2_raw h01 = __nv_cvt_fp8x2_to_halfraw2((__nv_fp8x2_storage_t)(hw & 0xffffu), __NV_E4M3);
    __half2_raw h23 = __nv_cvt_fp8x2_to_halfraw2((__nv_fp8x2_storage_t)(hw >> 16), __NV_E4M3);
    __half2 q0 = __hmul2(*(__half2*)&t01, *(__half2*)&h01);
    __half2 q1 = __hmul2(*(__half2*)&t23, *(__half2*)&h23);
    float2 f0 = __half22float2(q0);
    float2 f1 = __half22float2(q1);
    a0 = fmaf(f0.x, ex, a0);
    a1 = fmaf(f0.y, ex, a1);
    a2 = fmaf(f1.x, ex, a2);
    a3 = fmaf(f1.y, ex, a3);
}

__global__ void __launch_bounds__(256) gather_v(int l) {
    const unsigned* Tp = (const unsigned*)g_T8 + (size_t)l * (TBL + 1) * 32;
    int wid = threadIdx.x >> 5, lane = threadIdx.x & 31;
    int n = blockIdx.x * 8 + wid;
    if (n >= NN) return;
    int beg = g_rowptr[n], end = g_rowptr[n + 1];
    float2 er = ((const float2*)g_er)[n];
    float a0 = 0.f, a1 = 0.f, a2 = 0.f, a3 = 0.f, exs = 0.f;
    const unsigned* hh = g_h8;
    for (int base = beg; base < end; base += 32) {
        int cnt = min(32, end - base);
        float u = 0.f, e0 = 0.f, e1 = 0.f;
        int s = 0;
        if (lane < cnt) {
            float2 su = g_su[base + lane];
            u = su.x;
            s = __float_as_int(su.y);
            float2 el = ((const float2*)g_el)[s];
            float ev0 = el.x + er.x; ev0 = ev0 > 0.f ? ev0 : 0.2f * ev0;
            float ev1 = el.y + er.y; ev1 = ev1 > 0.f ? ev1 : 0.2f * ev1;
            e0 = __expf(ev0);
            e1 = __expf(ev1);
        }
        int c = 0;
        for (; c + 2 <= cnt; c += 2) {
            float uc0 = __shfl_sync(0xffffffffu, u, c);
            int   sc0 = __shfl_sync(0xffffffffu, s, c);
            float p00 = __shfl_sync(0xffffffffu, e0, c);
            float p01 = __shfl_sync(0xffffffffu, e1, c);
            float uc1 = __shfl_sync(0xffffffffu, u, c + 1);
            int   sc1 = __shfl_sync(0xffffffffu, s, c + 1);
            float p10 = __shfl_sync(0xffffffffu, e0, c + 1);
            float p11 = __shfl_sync(0xffffffffu, e1, c + 1);
            int i0 = (int)(uc0 + 0.5f);
            int i1 = (int)(uc1 + 0.5f);
            unsigned tw0 = Tp[i0 * 32 + lane];
            unsigned hw0 = hh[sc0 * 32 + lane];
            unsigned tw1 = Tp[i1 * 32 + lane];
            unsigned hw1 = hh[sc1 * 32 + lane];
            float ex0 = (lane < 16) ? p00 : p01;
            float ex1 = (lane < 16) ? p10 : p11;
            edge_mul_acc(tw0, hw0, ex0, a0, a1, a2, a3);
            edge_mul_acc(tw1, hw1, ex1, a0, a1, a2, a3);
            exs += ex0 + ex1;
        }
        if (c < cnt) {
            float uc = __shfl_sync(0xffffffffu, u, c);
            int   sc = __shfl_sync(0xffffffffu, s, c);
            float p0 = __shfl_sync(0xffffffffu, e0, c);
            float p1 = __shfl_sync(0xffffffffu, e1, c);
            int i = (int)(uc + 0.5f);
            unsigned tw = Tp[i * 32 + lane];
            unsigned hw = hh[sc * 32 + lane];
            float ex = (lane < 16) ? p0 : p1;
            edge_mul_acc(tw, hw, ex, a0, a1, a2, a3);
            exs += ex;
        }
    }
    float inv = (exs > 0.f) ? 1.0f / exs : 0.f;
    float4 o;
    o.x = ssp(a0 * inv);
    o.y = ssp(a1 * inv);
    o.z = ssp(a2 * inv);
    o.w = ssp(a3 * inv);
    ((float4*)g_v)[n * 32 + lane] = o;
}

// ---------------- fused: mlp(layer l) + pre(layer l+1) ----------------
__global__ void __launch_bounds__(256) mlp_pre(const float* __restrict__ m1,
                                               const float* __restrict__ mb1,
                                               const float* __restrict__ m2,
                                               const float* __restrict__ mb2,
                                               const float* __restrict__ fcw,
                                               const float* __restrict__ al,
                                               const float* __restrict__ ar) {
    int n0 = blockIdx.x * 32;
    int t = threadIdx.x;
    __shared__ float vs[32 * 129];
    __shared__ float t1s[32 * 65];
    __shared__ float xs[32 * 65];
    __shared__ float els[64], ers[64];
    for (int i = t; i < 32 * 128; i += 256) {
        int node = n0 + (i >> 7);
        vs[(i >> 7) * 129 + (i & 127)] = (node < NN) ? g_v[node * 128 + (i & 127)] : 0.f;
    }
    if (t < 64) { els[t] = 0.f; ers[t] = 0.f; }
    __syncthreads();
    {
        int nA = t & 15, nB2 = nA + 16, cg = t >> 4;
        float aA0 = 0.f, aA1 = 0.f, aA2 = 0.f, aA3 = 0.f;
        float aB0 = 0.f, aB1 = 0.f, aB2 = 0.f, aB3 = 0.f;
        const float4* M1 = (const float4*)m1;
#pragma unroll 4
        for (int k = 0; k < 128; k++) {
            float xA = vs[nA * 129 + k];
            float xB = vs[nB2 * 129 + k];
            float4 w = M1[k * 16 + cg];
            aA0 = fmaf(xA, w.x, aA0); aB0 = fmaf(xB, w.x, aB0);
            aA1 = fmaf(xA, w.y, aA1); aB1 = fmaf(xB, w.y, aB1);
            aA2 = fmaf(xA, w.z, aA2); aB2 = fmaf(xB, w.z, aB2);
            aA3 = fmaf(xA, w.w, aA3); aB3 = fmaf(xB, w.w, aB3);
        }
        float4 b14 = ((const float4*)mb1)[cg];
        t1s[nA * 65 + cg * 4 + 0] = ssp(aA0 + b14.x);
        t1s[nA * 65 + cg * 4 + 1] = ssp(aA1 + b14.y);
        t1s[nA * 65 + cg * 4 + 2] = ssp(aA2 + b14.z);
        t1s[nA * 65 + cg * 4 + 3] = ssp(aA3 + b14.w);
        t1s[nB2 * 65 + cg * 4 + 0] = ssp(aB0 + b14.x);
        t1s[nB2 * 65 + cg * 4 + 1] = ssp(aB1 + b14.y);
        t1s[nB2 * 65 + cg * 4 + 2] = ssp(aB2 + b14.z);
        t1s[nB2 * 65 + cg * 4 + 3] = ssp(aB3 + b14.w);
        __syncthreads();
        aA0 = aA1 = aA2 = aA3 = 0.f;
        aB0 = aB1 = aB2 = aB3 = 0.f;
        const float4* M2 = (const float4*)m2;
#pragma unroll 4
        for (int k = 0; k < 64; k++) {
            float xA = t1s[nA * 65 + k];
            float xB = t1s[nB2 * 65 + k];
            float4 w = M2[k * 16 + cg];
            aA0 = fmaf(xA, w.x, aA0); aB0 = fmaf(xB, w.x, aB0);
            aA1 = fmaf(xA, w.y, aA1); aB1 = fmaf(xB, w.y, aB1);
            aA2 = fmaf(xA, w.z, aA2); aB2 = fmaf(xB, w.z, aB2);
            aA3 = fmaf(xA, w.w, aA3); aB3 = fmaf(xB, w.w, aB3);
        }
        float4 b24 = ((const float4*)mb2)[cg];
        bool vA = (n0 + nA) < NN, vB = (n0 + nB2) < NN;
        float4 xA4 = make_float4(0.f, 0.f, 0.f, 0.f);
        float4 xB4 = make_float4(0.f, 0.f, 0.f, 0.f);
        if (vA) xA4 = ((float4*)g_x)[(n0 + nA) * 16 + cg];
        if (vB) xB4 = ((float4*)g_x)[(n0 + nB2) * 16 + cg];
        xA4.x += aA0 + b24.x; xA4.y += aA1 + b24.y;
        xA4.z += aA2 + b24.z; xA4.w += aA3 + b24.w;
        xB4.x += aB0 + b24.x; xB4.y += aB1 + b24.y;
        xB4.z += aB2 + b24.z; xB4.w += aB3 + b24.w;
        if (vA) ((float4*)g_x)[(n0 + nA) * 16 + cg] = xA4;
        if (vB) ((float4*)g_x)[(n0 + nB2) * 16 + cg] = xB4;
        xs[nA * 65 + cg * 4 + 0] = xA4.x;
        xs[nA * 65 + cg * 4 + 1] = xA4.y;
        xs[nA * 65 + cg * 4 + 2] = xA4.z;
        xs[nA * 65 + cg * 4 + 3] = xA4.w;
        xs[nB2 * 65 + cg * 4 + 0] = xB4.x;
        xs[nB2 * 65 + cg * 4 + 1] = xB4.y;
        xs[nB2 * 65 + cg * 4 + 2] = xB4.z;
        xs[nB2 * 65 + cg * 4 + 3] = xB4.w;
    }
    __syncthreads();
    PRE_PHASE(fcw, al, ar)
}

// ---------------- fused: mlp(last layer) + output head ----------------
__global__ void __launch_bounds__(256) mlp_out(const float* __restrict__ m1,
                                               const float* __restrict__ mb1,
                                               const float* __restrict__ m2,
                                               const float* __restrict__ mb2,
                                               const float* __restrict__ w1o,
                                               const float* __restrict__ b1o,
                                               const float* __restrict__ w2o,
                                               const float* __restrict__ b2o,
                                               const int* __restrict__ gid,
                                               float* __restrict__ out) {
    int n0 = blockIdx.x * 16;          // 3125 blocks exact
    int t = threadIdx.x;
    __shared__ float vs[16 * 129];
    __shared__ float t1s[16 * 65];
    __shared__ float xs[16 * 65];
    __shared__ float sred[16][17];
    for (int i = t; i < 16 * 128; i += 256)
        vs[(i >> 7) * 129 + (i & 127)] = g_v[n0 * 128 + i];
    __syncthreads();
    int n = t & 15, cg = t >> 4;
    {
        float a0 = 0.f, a1 = 0.f, a2 = 0.f, a3 = 0.f;
        const float4* M1 = (const float4*)m1;
#pragma unroll 4
        for (int k = 0; k < 128; k++) {
            float xv = vs[n * 129 + k];
            float4 w = M1[k * 16 + cg];
            a0 = fmaf(xv, w.x, a0);
            a1 = fmaf(xv, w.y, a1);
            a2 = fmaf(xv, w.z, a2);
            a3 = fmaf(xv, w.w, a3);
        }
        float4 b14 = ((const float4*)mb1)[cg];
        t1s[n * 65 + cg * 4 + 0] = ssp(a0 + b14.x);
        t1s[n * 65 + cg * 4 + 1] = ssp(a1 + b14.y);
        t1s[n * 65 + cg * 4 + 2] = ssp(a2 + b14.z);
        t1s[n * 65 + cg * 4 + 3] = ssp(a3 + b14.w);
        __syncthreads();
        a0 = a1 = a2 = a3 = 0.f;
        const float4* M2 = (const float4*)m2;
#pragma unroll 4
        for (int k = 0; k < 64; k++) {
            float xv = t1s[n * 65 + k];
            float4 w = M2[k * 16 + cg];
            a0 = fmaf(xv, w.x, a0);
            a1 = fmaf(xv, w.y, a1);
            a2 = fmaf(xv, w.z, a2);
            a3 = fmaf(xv, w.w, a3);
        }
        float4 b24 = ((const float4*)mb2)[cg];
        float4 x4 = ((const float4*)g_x)[(n0 + n) * 16 + cg];
        xs[n * 65 + cg * 4 + 0] = x4.x + a0 + b24.x;
        xs[n * 65 + cg * 4 + 1] = x4.y + a1 + b24.y;
        xs[n * 65 + cg * 4 + 2] = x4.z + a2 + b24.z;
        xs[n * 65 + cg * 4 + 3] = x4.w + a3 + b24.w;
    }
    __syncthreads();
    float acc[8];
#pragma unroll
    for (int j = 0; j < 8; j++) acc[j] = 0.f;
    const float4* W4 = (const float4*)w1o;
#pragma unroll 4
    for (int k = 0; k < 64; k++) {
        float xv = xs[n * 65 + k];
        float4 wa = W4[k * 32 + cg * 2];
        float4 wb = W4[k * 32 + cg * 2 + 1];
        acc[0] = fmaf(xv, wa.x, acc[0]);
        acc[1] = fmaf(xv, wa.y, acc[1]);
        acc[2] = fmaf(xv, wa.z, acc[2]);
        acc[3] = fmaf(xv, wa.w, acc[3]);
        acc[4] = fmaf(xv, wb.x, acc[4]);
        acc[5] = fmaf(xv, wb.y, acc[5]);
        acc[6] = fmaf(xv, wb.z, acc[6]);
        acc[7] = fmaf(xv, wb.w, acc[7]);
    }
    float4 b1a = ((const float4*)b1o)[cg * 2];
    float4 b1b = ((const float4*)b1o)[cg * 2 + 1];
    float4 w2a = ((const float4*)w2o)[cg * 2];
    float4 w2b = ((const float4*)w2o)[cg * 2 + 1];
    float p = ssp(acc[0] + b1a.x) * w2a.x + ssp(acc[1] + b1a.y) * w2a.y
            + ssp(acc[2] + b1a.z) * w2a.z + ssp(acc[3] + b1a.w) * w2a.w
            + ssp(acc[4] + b1b.x) * w2b.x + ssp(acc[5] + b1b.y) * w2b.y
            + ssp(acc[6] + b1b.z) * w2b.z + ssp(acc[7] + b1b.w) * w2b.w;
    sred[cg][n] = p;
    __syncthreads();
    if (t < 16) {
        float s = b2o[0];
#pragma unroll
        for (int c = 0; c < 16; c++) s += sred[c][t];
        atomicAdd(&out[gid[n0 + t]], s);
    }
}

extern "C" void kernel_launch(void* const* d_in, const int* in_sizes, int n_in,
                              void* d_out, int out_size) {
    const float* R    = (const float*)d_in[0];
    const int*   Z    = (const int*)d_in[1];
    const int*   src  = (const int*)d_in[2];
    const int*   dst  = (const int*)d_in[3];
    const int*   gid  = (const int*)d_in[4];
    const float* emb  = (const float*)d_in[5];
    const float* off  = (const float*)d_in[6];
    const float* wid  = (const float*)d_in[7];
    const float* fcw  = (const float*)d_in[8];
    const float* al   = (const float*)d_in[9];
    const float* ar   = (const float*)d_in[10];
    const float* fw1  = (const float*)d_in[11];
    const float* fb1  = (const float*)d_in[12];
    const float* fw2  = (const float*)d_in[13];
    const float* fb2  = (const float*)d_in[14];
    const float* m1   = (const float*)d_in[15];
    const float* mb1  = (const float*)d_in[16];
    const float* m2   = (const float*)d_in[17];
    const float* mb2  = (const float*)d_in[18];
    const float* ow1  = (const float*)d_in[19];
    const float* ob1  = (const float*)d_in[20];
    const float* ow2  = (const float*)d_in[21];
    const float* ob2  = (const float*)d_in[22];
    float* out = (float*)d_out;

    zero_deg<<<(NN + 255) / 256, 256>>>(out);
    build_tables<<<LLAYERS * TBLK, 128>>>(off, wid, fw1, fb1, fw2, fb2);
    count_deg<<<(EE + 255) / 256, 256>>>(dst);
    scan1<<<SCAN_BLKS, 1024>>>();
    scan3<<<(NN + 255) / 256, 256>>>();
    scatter_kernel<<<(EE + 255) / 256, 256>>>(R, src, dst);

    pre_first<<<(NN + 31) / 32, 256>>>(Z, emb, fcw, al, ar);
    gather_v<<<(NN + 7) / 8, 256>>>(0);
    mlp_pre<<<(NN + 31) / 32, 256>>>(m1, mb1, m2, mb2,
                                     fcw + 1 * DD * HD, al + 1 * 2 * DD, ar + 1 * 2 * DD);
    gather_v<<<(NN + 7) / 8, 256>>>(1);
    mlp_pre<<<(NN + 31) / 32, 256>>>(m1 + 1 * HD * DD, mb1 + 1 * DD, m2 + 1 * DD * DD, mb2 + 1 * DD,
                                     fcw + 2 * DD * HD, al + 2 * 2 * DD, ar + 2 * 2 * DD);
    gather_v<<<(NN + 7) / 8, 256>>>(2);
    mlp_out<<<NN / 16, 256>>>(m1 + 2 * HD * DD, mb1 + 2 * DD, m2 + 2 * DD * DD, mb2 + 2 * DD,
                              ow1, ob1, ow2, ob2, gid, out);
}